// round 8
// baseline (speedup 1.0000x reference)
#include <cuda_runtime.h>
#include <cstdint>
#include <cstddef>

// Fused e3nn per-irrep linear, tf32 mma.sync (sm_103-safe PTX only).
// R8: R6 skeleton (256 thr, 2 CTA/SM) + 3-stage cp.async pipeline with ONE
// __syncthreads per k-tile + n-major B loaded via ldmatrix.x4.
//   out[b, off + w*D + i] = PW * sum_u W[u,w] * x[b, off + u*D + i]  (+bias, D==1)

static constexpr int MUL   = 512;
static constexpr int DIM   = 4608;
static constexpr int BATCH = 4096;
static constexpr int BN  = 128;
static constexpr int BK  = 16;
static constexpr int NKT = MUL / BK;          // 32 k-tiles
// PW * (1 + 2^-10): compensates fp32->tf32 truncation of both operands.
static constexpr float PWC = 0.04423733224f;

static constexpr int LDKB  = 80;              // A row stride bytes (20 floats)
static constexpr int LDNB  = 80;              // B row stride bytes (n-major rows)
static constexpr int A_REG = 128 * LDKB;      // 10240 (max R=128)
static constexpr int B_REG = BN * LDNB;       // 10240
static constexpr int STAGE = A_REG + B_REG;   // 20480
static constexpr int NSTG  = 3;
static constexpr int SM_TOTAL = NSTG * STAGE; // 61440

__device__ __forceinline__ void cp16(uint32_t s, const void* g) {
    asm volatile("cp.async.cg.shared.global [%0], [%1], 16;" :: "r"(s), "l"(g));
}
__device__ __forceinline__ void cp4(uint32_t s, const void* g) {
    asm volatile("cp.async.ca.shared.global [%0], [%1], 4;" :: "r"(s), "l"(g));
}
__device__ __forceinline__ void cp_commit() {
    asm volatile("cp.async.commit_group;" ::: "memory");
}
__device__ __forceinline__ void cp_wait1() {
    asm volatile("cp.async.wait_group 1;" ::: "memory");
}
__device__ __forceinline__ void ldmx4(uint32_t& r0, uint32_t& r1, uint32_t& r2,
                                      uint32_t& r3, uint32_t addr) {
    asm volatile("ldmatrix.sync.aligned.m8n8.x4.shared.b16 {%0,%1,%2,%3}, [%4];"
                 : "=r"(r0), "=r"(r1), "=r"(r2), "=r"(r3) : "r"(addr));
}
__device__ __forceinline__ void mma_tf32(
    float& c0, float& c1, float& c2, float& c3,
    uint32_t a0, uint32_t a1, uint32_t a2, uint32_t a3,
    uint32_t b0, uint32_t b1)
{
    asm volatile(
        "mma.sync.aligned.m16n8k8.row.col.f32.tf32.tf32.f32 "
        "{%0,%1,%2,%3}, {%4,%5,%6,%7}, {%8,%9}, {%0,%1,%2,%3};"
        : "+f"(c0), "+f"(c1), "+f"(c2), "+f"(c3)
        : "r"(a0), "r"(a1), "r"(a2), "r"(a3), "r"(b0), "r"(b1));
}

template<int D, int R, int NWM, int NWN>
__device__ __forceinline__ void run_tile(
    const float* __restrict__ x, const float* __restrict__ w,
    const float* __restrict__ bias, float* __restrict__ out,
    int mt, int nt, int off, uint32_t smb)
{
    constexpr int BM    = R / D;
    constexpr int WM    = R / NWM;
    constexpr int WN    = BN / NWN;
    constexpr int MFRAG = WM / 16;
    constexpr int NFRAG = WN / 8;
    constexpr int NA    = (D == 1) ? (R * BK / 4 / 256) : (BM * BK * D / 256);
    constexpr int NB    = BK * BN / 256;          // 8 B elements per thread (cp4)
    static_assert(NWM * NWN == 8 && WM % 16 == 0 && NFRAG % 2 == 0, "layout");

    const int tid  = threadIdx.x;
    const int wid  = tid >> 5;
    const int lane = tid & 31;
    const int g    = lane >> 2;
    const int tig  = lane & 3;
    const int wm   = wid % NWM;
    const int wn   = wid / NWM;
    const int b0   = mt * BM;
    const int w0   = nt * BN;

    // ---- tile-invariant fill assignments ----
    const float* const xb = x + (size_t)b0 * DIM + off;
    int      aoffg[NA];
    uint32_t aoffs[NA];
    #pragma unroll
    for (int e = 0; e < NA; e++) {
        const int v = tid + e * 256;
        if constexpr (D == 1) {
            const int r = v >> 2, ch = v & 3;
            aoffg[e] = r * DIM + ch * 4;
            aoffs[e] = (uint32_t)(r * LDKB + ch * 16);
        } else {
            const int bl = v / (BK * D);
            const int j  = v % (BK * D);
            const int k  = j / D;
            const int r  = bl * D + j % D;
            aoffg[e] = bl * DIM + j;
            aoffs[e] = (uint32_t)(r * LDKB + k * 4);
        }
    }
    // B: global [k][n] (n contiguous) -> smem n-major Bs[n][k]
    const float* const wb = w + w0;
    int      boffg[NB];
    uint32_t boffs[NB];
    #pragma unroll
    for (int e = 0; e < NB; e++) {
        const int v = tid + e * 256;          // coalesced along n per 128 threads
        const int k = v >> 7, n = v & 127;
        boffg[e] = k * MUL + n;
        boffs[e] = (uint32_t)(A_REG + n * LDNB + k * 4);
    }
    // ldmatrix lane-invariant offsets
    const int a_row = (lane & 7) + ((lane >> 3) & 1) * 8;     // A matrix rows
    const int a_hi  = (lane >> 4) * 16;                       // A k-half 16B
    const uint32_t a_lm = (uint32_t)((wm * WM + a_row) * LDKB + a_hi);
    const int b_row = (lane & 7) + (lane >> 4) * 8;           // B n within pair
    const int b_kh  = ((lane >> 3) & 1) * 16;                 // B k-half 16B
    const uint32_t b_lm = (uint32_t)(A_REG + (wn * WN + b_row) * LDNB + b_kh);

    float acc[MFRAG][NFRAG][4] = {};

    uint32_t stg[NSTG];
    #pragma unroll
    for (int s = 0; s < NSTG; s++) stg[s] = smb + s * STAGE;

    auto load_tile = [&](int t, uint32_t base) {
        const int ta = t * (BK * D);
        #pragma unroll
        for (int e = 0; e < NA; e++) {
            if constexpr (D == 1) cp16(base + aoffs[e], xb + aoffg[e] + ta);
            else                  cp4 (base + aoffs[e], xb + aoffg[e] + ta);
        }
        const int tb = t * (BK * MUL);
        #pragma unroll
        for (int e = 0; e < NB; e++)
            cp4(base + boffs[e], wb + boffg[e] + tb);
    };

    load_tile(0, stg[0]); cp_commit();
    load_tile(1, stg[1]); cp_commit();

    int cur = 0, nxt = 2;
    for (int t = 0; t < NKT; t++) {
        cp_wait1();
        __syncthreads();
        if (t + 2 < NKT) load_tile(t + 2, stg[nxt]);
        cp_commit();

        const uint32_t Ac = stg[cur];
        #pragma unroll
        for (int kk = 0; kk < BK; kk += 8) {
            uint32_t afr[MFRAG][4];
            #pragma unroll
            for (int m = 0; m < MFRAG; m++)
                ldmx4(afr[m][0], afr[m][1], afr[m][2], afr[m][3],
                      Ac + a_lm + (uint32_t)(m * 16 * LDKB + kk * 4));
            uint32_t bfr[NFRAG][2];
            #pragma unroll
            for (int j = 0; j < NFRAG; j += 2)
                ldmx4(bfr[j][0], bfr[j][1], bfr[j + 1][0], bfr[j + 1][1],
                      Ac + b_lm + (uint32_t)(j * 8 * LDNB + kk * 4));
            #pragma unroll
            for (int m = 0; m < MFRAG; m++)
                #pragma unroll
                for (int n = 0; n < NFRAG; n++)
                    mma_tf32(acc[m][n][0], acc[m][n][1], acc[m][n][2], acc[m][n][3],
                             afr[m][0], afr[m][1], afr[m][2], afr[m][3],
                             bfr[n][0], bfr[n][1]);
        }
        cur = (cur + 1 == NSTG) ? 0 : cur + 1;
        nxt = (nxt + 1 == NSTG) ? 0 : nxt + 1;
    }

    // ---- epilogue (truncation compensation folded into PWC) ----
    #pragma unroll
    for (int m = 0; m < MFRAG; m++) {
        #pragma unroll
        for (int half = 0; half < 2; half++) {
            const int row = wm * WM + m * 16 + g + half * 8;
            const int b   = b0 + row / D;
            const int i   = row % D;
            float* orow = out + (size_t)b * DIM + off + i;
            #pragma unroll
            for (int n = 0; n < NFRAG; n++) {
                const int col = wn * WN + n * 8 + 2 * tig;
                #pragma unroll
                for (int e = 0; e < 2; e++) {
                    const int wc = w0 + col + e;
                    float v = acc[m][n][half * 2 + e] * PWC;
                    if (D == 1) v += bias[wc];
                    orow[(size_t)wc * D] = v;
                }
            }
        }
    }
}

// D=1 tile 128x128 -> 128 blocks; D=3 96x128 -> 512; D=5 80x128 -> 1024
static constexpr int NB0 = (BATCH / 128) * (MUL / BN);
static constexpr int NB1 = (BATCH / 32)  * (MUL / BN);
static constexpr int NB2 = (BATCH / 16)  * (MUL / BN);

__global__ __launch_bounds__(256, 2) void fused_irrep_kernel(
    const float* __restrict__ x,
    const float* __restrict__ w0, const float* __restrict__ w1,
    const float* __restrict__ w2, const float* __restrict__ b0,
    float* __restrict__ out)
{
    extern __shared__ __align__(16) char sm[];
    const uint32_t smb = (uint32_t)__cvta_generic_to_shared(sm);
    const int bx = blockIdx.x;
    if (bx < NB0) {
        run_tile<1, 128, 2, 4>(x, w0, b0, out, bx >> 2, bx & 3, 0, smb);
    } else if (bx < NB0 + NB1) {
        const int i = bx - NB0;
        run_tile<3,  96, 2, 4>(x, w1, b0, out, i >> 2, i & 3, 512, smb);
    } else {
        const int i = bx - NB0 - NB1;
        run_tile<5,  80, 1, 8>(x, w2, b0, out, i >> 2, i & 3, 2048, smb);
    }
}

extern "C" void kernel_launch(void* const* d_in, const int* in_sizes, int n_in,
                              void* d_out, int out_size)
{
    const float* x  = (const float*)d_in[0];
    const float* w0 = (const float*)d_in[1];
    const float* w1 = (const float*)d_in[2];
    const float* w2 = (const float*)d_in[3];
    const float* b0 = (const float*)d_in[4];
    float* out = (float*)d_out;

    cudaFuncSetAttribute(fused_irrep_kernel,
                         cudaFuncAttributeMaxDynamicSharedMemorySize, SM_TOTAL);
    fused_irrep_kernel<<<NB0 + NB1 + NB2, 256, SM_TOTAL>>>(x, w0, w1, w2, b0, out);
}

// round 9
// speedup vs baseline: 1.1467x; 1.1467x over previous
#include <cuda_runtime.h>
#include <cstdint>
#include <cstddef>

// Fused e3nn per-irrep linear, tf32 mma.sync (sm_103-safe PTX only).
// R9: pre-kernel transposes W -> n-major tf32(RN) scratch; main kernel uses
// ldmatrix.x4 for BOTH A and B fragments, cp16-only B fill, 3-stage cp.async
// pipeline with ONE __syncthreads per k-tile. 256 thr, 2 CTAs/SM.
//   out[b, off + w*D + i] = PW * sum_u W[u,w] * x[b, off + u*D + i]  (+bias, D==1)

static constexpr int MUL   = 512;
static constexpr int DIM   = 4608;
static constexpr int BATCH = 4096;
static constexpr int BN  = 128;
static constexpr int BK  = 16;
static constexpr int NKT = MUL / BK;          // 32 k-tiles
// PW * (1 + 2^-11): W is RN-rounded in the transpose pass; only A suffers
// HW RZ truncation (mean (1-2^-11)) inside the mma.
static constexpr float PWC1 = 0.04421575535f;

static constexpr int LDKB  = 80;              // A row stride bytes (20 floats)
static constexpr int LDNB  = 80;              // B n-row stride bytes (16 fl + pad)
static constexpr int A_REG = 128 * LDKB;      // 10240 (max R=128)
static constexpr int B_REG = BN * LDNB;       // 10240
static constexpr int STAGE = A_REG + B_REG;   // 20480
static constexpr int NSTG  = 3;
static constexpr int SM_TOTAL = NSTG * STAGE; // 61440

__device__ float wT_buf[3 * MUL * MUL];       // n-major, tf32-RN-rounded weights

__device__ __forceinline__ float to_tf32(float x) {
    asm("cvt.rna.tf32.f32 %0, %0;" : "+f"(x)); return x;
}
__device__ __forceinline__ void cp16(uint32_t s, const void* g) {
    asm volatile("cp.async.cg.shared.global [%0], [%1], 16;" :: "r"(s), "l"(g));
}
__device__ __forceinline__ void cp4(uint32_t s, const void* g) {
    asm volatile("cp.async.ca.shared.global [%0], [%1], 4;" :: "r"(s), "l"(g));
}
__device__ __forceinline__ void cp_commit() {
    asm volatile("cp.async.commit_group;" ::: "memory");
}
__device__ __forceinline__ void cp_wait1() {
    asm volatile("cp.async.wait_group 1;" ::: "memory");
}
__device__ __forceinline__ void ldmx4(uint32_t& r0, uint32_t& r1, uint32_t& r2,
                                      uint32_t& r3, uint32_t addr) {
    asm volatile("ldmatrix.sync.aligned.m8n8.x4.shared.b16 {%0,%1,%2,%3}, [%4];"
                 : "=r"(r0), "=r"(r1), "=r"(r2), "=r"(r3) : "r"(addr));
}
__device__ __forceinline__ void mma_tf32(
    float& c0, float& c1, float& c2, float& c3,
    uint32_t a0, uint32_t a1, uint32_t a2, uint32_t a3,
    uint32_t b0, uint32_t b1)
{
    asm volatile(
        "mma.sync.aligned.m16n8k8.row.col.f32.tf32.tf32.f32 "
        "{%0,%1,%2,%3}, {%4,%5,%6,%7}, {%8,%9}, {%0,%1,%2,%3};"
        : "+f"(c0), "+f"(c1), "+f"(c2), "+f"(c3)
        : "r"(a0), "r"(a1), "r"(a2), "r"(a3), "r"(b0), "r"(b1));
}

// ---- pre-pass: wT[m][n][k] = tf32_rn(w_m[k][n]) ----
__global__ void transpose_w_kernel(const float* __restrict__ w0,
                                   const float* __restrict__ w1,
                                   const float* __restrict__ w2)
{
    __shared__ float tile[32][33];
    const int m  = blockIdx.z;
    const float* src = (m == 0) ? w0 : (m == 1) ? w1 : w2;
    float* dst = wT_buf + m * MUL * MUL;
    const int kb = blockIdx.x * 32, nb = blockIdx.y * 32;
    #pragma unroll
    for (int i = threadIdx.y; i < 32; i += 8)
        tile[i][threadIdx.x] = src[(size_t)(kb + i) * MUL + nb + threadIdx.x];
    __syncthreads();
    #pragma unroll
    for (int i = threadIdx.y; i < 32; i += 8)
        dst[(size_t)(nb + i) * MUL + kb + threadIdx.x] = to_tf32(tile[threadIdx.x][i]);
}

template<int D, int R, int NWM, int NWN>
__device__ __forceinline__ void run_tile(
    const float* __restrict__ x, const float* __restrict__ wT,
    const float* __restrict__ bias, float* __restrict__ out,
    int mt, int nt, int off, uint32_t smb)
{
    constexpr int BM    = R / D;
    constexpr int WM    = R / NWM;
    constexpr int WN    = BN / NWN;
    constexpr int MFRAG = WM / 16;
    constexpr int NFRAG = WN / 8;
    constexpr int NA    = (D == 1) ? (R * BK / 4 / 256) : (BM * BK * D / 256);
    static_assert(NWM * NWN == 8 && WM % 16 == 0 && NFRAG % 2 == 0, "layout");

    const int tid  = threadIdx.x;
    const int wid  = tid >> 5;
    const int lane = tid & 31;
    const int g    = lane >> 2;
    const int tig  = lane & 3;
    const int wm   = wid % NWM;
    const int wn   = wid / NWM;
    const int b0   = mt * BM;
    const int w0   = nt * BN;

    // ---- tile-invariant fill assignments ----
    const float* const xb = x + (size_t)b0 * DIM + off;
    int      aoffg[NA];
    uint32_t aoffs[NA];
    #pragma unroll
    for (int e = 0; e < NA; e++) {
        const int v = tid + e * 256;
        if constexpr (D == 1) {
            const int r = v >> 2, ch = v & 3;
            aoffg[e] = r * DIM + ch * 4;
            aoffs[e] = (uint32_t)(r * LDKB + ch * 16);
        } else {
            const int bl = v / (BK * D);
            const int j  = v % (BK * D);
            const int k  = j / D;
            const int r  = bl * D + j % D;
            aoffg[e] = bl * DIM + j;
            aoffs[e] = (uint32_t)(r * LDKB + k * 4);
        }
    }
    // B: wT is n-major [n][k]; per stage each n-row needs BK=16 floats (64B)
    const float* const wb = wT + (size_t)w0 * MUL;
    int      boffg[2];
    uint32_t boffs[2];
    #pragma unroll
    for (int e = 0; e < 2; e++) {
        const int v  = tid + e * 256;       // 512 chunks: n = v>>2, kq = v&3
        const int n  = v >> 2, kq = v & 3;
        boffg[e] = n * MUL + kq * 4;
        boffs[e] = (uint32_t)(A_REG + n * LDNB + kq * 16);
    }
    // ldmatrix lane-invariant offsets (A verified in R6, B in R8)
    const int a_row = (lane & 7) + ((lane >> 3) & 1) * 8;
    const int a_hi  = (lane >> 4) * 16;
    const uint32_t a_lm = (uint32_t)((wm * WM + a_row) * LDKB + a_hi);
    const int b_row = (lane & 7) + (lane >> 4) * 8;
    const int b_kh  = ((lane >> 3) & 1) * 16;
    const uint32_t b_lm = (uint32_t)(A_REG + (wn * WN + b_row) * LDNB + b_kh);

    float acc[MFRAG][NFRAG][4] = {};

    uint32_t stg[NSTG];
    #pragma unroll
    for (int s = 0; s < NSTG; s++) stg[s] = smb + s * STAGE;

    auto load_tile = [&](int t, uint32_t base) {
        const int ta = t * (BK * D);
        #pragma unroll
        for (int e = 0; e < NA; e++) {
            if constexpr (D == 1) cp16(base + aoffs[e], xb + aoffg[e] + ta);
            else                  cp4 (base + aoffs[e], xb + aoffg[e] + ta);
        }
        const int tb = t * BK;              // 16 floats into each n-row
        #pragma unroll
        for (int e = 0; e < 2; e++)
            cp16(base + boffs[e], wb + boffg[e] + tb);
    };

    load_tile(0, stg[0]); cp_commit();
    load_tile(1, stg[1]); cp_commit();

    int cur = 0, nxt = 2;
    for (int t = 0; t < NKT; t++) {
        cp_wait1();
        __syncthreads();                     // stage t ready; buffer nxt vacated
        if (t + 2 < NKT) load_tile(t + 2, stg[nxt]);
        cp_commit();

        const uint32_t Ac = stg[cur];
        #pragma unroll
        for (int kk = 0; kk < BK; kk += 8) {
            uint32_t afr[MFRAG][4];
            #pragma unroll
            for (int m = 0; m < MFRAG; m++)
                ldmx4(afr[m][0], afr[m][1], afr[m][2], afr[m][3],
                      Ac + a_lm + (uint32_t)(m * 16 * LDKB + kk * 4));
            uint32_t bfr[NFRAG][2];
            #pragma unroll
            for (int j = 0; j < NFRAG; j += 2)
                ldmx4(bfr[j][0], bfr[j][1], bfr[j + 1][0], bfr[j + 1][1],
                      Ac + b_lm + (uint32_t)(j * 8 * LDNB + kk * 4));
            #pragma unroll
            for (int m = 0; m < MFRAG; m++)
                #pragma unroll
                for (int n = 0; n < NFRAG; n++)
                    mma_tf32(acc[m][n][0], acc[m][n][1], acc[m][n][2], acc[m][n][3],
                             afr[m][0], afr[m][1], afr[m][2], afr[m][3],
                             bfr[n][0], bfr[n][1]);
        }
        cur = (cur + 1 == NSTG) ? 0 : cur + 1;
        nxt = (nxt + 1 == NSTG) ? 0 : nxt + 1;
    }

    // ---- epilogue (A-side truncation compensation folded into PWC1) ----
    #pragma unroll
    for (int m = 0; m < MFRAG; m++) {
        #pragma unroll
        for (int half = 0; half < 2; half++) {
            const int row = wm * WM + m * 16 + g + half * 8;
            const int b   = b0 + row / D;
            const int i   = row % D;
            float* orow = out + (size_t)b * DIM + off + i;
            #pragma unroll
            for (int n = 0; n < NFRAG; n++) {
                const int col = wn * WN + n * 8 + 2 * tig;
                #pragma unroll
                for (int e = 0; e < 2; e++) {
                    const int wc = w0 + col + e;
                    float v = acc[m][n][half * 2 + e] * PWC1;
                    if (D == 1) v += bias[wc];
                    orow[(size_t)wc * D] = v;
                }
            }
        }
    }
}

// D=1 tile 128x128 -> 128 blocks; D=3 96x128 -> 512; D=5 80x128 -> 1024
static constexpr int NB0 = (BATCH / 128) * (MUL / BN);
static constexpr int NB1 = (BATCH / 32)  * (MUL / BN);
static constexpr int NB2 = (BATCH / 16)  * (MUL / BN);

__global__ __launch_bounds__(256, 2) void fused_irrep_kernel(
    const float* __restrict__ x, const float* __restrict__ b0,
    float* __restrict__ out)
{
    extern __shared__ __align__(16) char sm[];
    const uint32_t smb = (uint32_t)__cvta_generic_to_shared(sm);
    const int bx = blockIdx.x;
    if (bx < NB0) {
        run_tile<1, 128, 2, 4>(x, wT_buf,               b0, out,
                               bx >> 2, bx & 3, 0, smb);
    } else if (bx < NB0 + NB1) {
        const int i = bx - NB0;
        run_tile<3,  96, 2, 4>(x, wT_buf + MUL * MUL,   b0, out,
                               i >> 2, i & 3, 512, smb);
    } else {
        const int i = bx - NB0 - NB1;
        run_tile<5,  80, 1, 8>(x, wT_buf + 2 * MUL * MUL, b0, out,
                               i >> 2, i & 3, 2048, smb);
    }
}

extern "C" void kernel_launch(void* const* d_in, const int* in_sizes, int n_in,
                              void* d_out, int out_size)
{
    const float* x  = (const float*)d_in[0];
    const float* w0 = (const float*)d_in[1];
    const float* w1 = (const float*)d_in[2];
    const float* w2 = (const float*)d_in[3];
    const float* b0 = (const float*)d_in[4];
    float* out = (float*)d_out;

    transpose_w_kernel<<<dim3(MUL / 32, MUL / 32, 3), dim3(32, 8)>>>(w0, w1, w2);
    cudaFuncSetAttribute(fused_irrep_kernel,
                         cudaFuncAttributeMaxDynamicSharedMemorySize, SM_TOTAL);
    fused_irrep_kernel<<<NB0 + NB1 + NB2, 256, SM_TOTAL>>>(x, b0, out);
}

// round 10
// speedup vs baseline: 1.7495x; 1.5257x over previous
#include <cuda_runtime.h>
#include <cuda_fp16.h>
#include <cstdint>
#include <cstddef>

// Fused e3nn per-irrep linear, fp16 mma.sync m16n8k16 + fp32 accum.
// R10: pre-pass converts x -> per-irrep GEMM-layout fp16 x2[r][k] (kills the
// D>1 de-interleave scatter forever) and W -> n-major fp16 wT2. Main kernel:
// all-cp.async fill, ldmatrix.x4 A+B, BK=32, 3-stage 1-barrier pipeline.
//   out[b, off + w*D + i] = PW * sum_u W[u,w] * x[b, off + u*D + i]  (+bias, D==1)

static constexpr int MUL   = 512;
static constexpr int DIM   = 4608;
static constexpr int BATCH = 4096;
static constexpr int BN  = 128;
static constexpr int BK  = 32;
static constexpr int NKT = MUL / BK;          // 16 k-tiles
static constexpr float PW = 0.04419417382415922f;  // 512^-0.5 (no compensation: RN both sides)

static constexpr int LDA   = 80;              // bytes per A row (32 halves + pad)
static constexpr int LDB   = 80;              // bytes per B n-row
static constexpr int A_REG = 160 * LDA;       // max R = 160 -> 12800 B
static constexpr int B_REG = BN * LDB;        // 10240 B
static constexpr int STAGE = A_REG + B_REG;   // 23040
static constexpr int NSTG  = 3;
static constexpr int SM_TOTAL = NSTG * STAGE; // 69120 B

// x2: per-irrep row-major fp16 [r][512], r=(b,i). Regions: D=1 rows 4096,
// D=3 rows 12288, D=5 rows 20480. Total 36864 rows.
static constexpr int X2_R1 = 0;
static constexpr int X2_R3 = 4096;
static constexpr int X2_R5 = 4096 + 12288;
__device__ __half x2_buf[36864 * MUL];        // 37.75 MB scratch
__device__ __half wT2_buf[3 * MUL * MUL];     // n-major fp16 weights

__device__ __forceinline__ void cp16(uint32_t s, const void* g) {
    asm volatile("cp.async.cg.shared.global [%0], [%1], 16;" :: "r"(s), "l"(g));
}
__device__ __forceinline__ void cp_commit() {
    asm volatile("cp.async.commit_group;" ::: "memory");
}
__device__ __forceinline__ void cp_wait1() {
    asm volatile("cp.async.wait_group 1;" ::: "memory");
}
__device__ __forceinline__ void ldmx4(uint32_t& r0, uint32_t& r1, uint32_t& r2,
                                      uint32_t& r3, uint32_t addr) {
    asm volatile("ldmatrix.sync.aligned.m8n8.x4.shared.b16 {%0,%1,%2,%3}, [%4];"
                 : "=r"(r0), "=r"(r1), "=r"(r2), "=r"(r3) : "r"(addr));
}
__device__ __forceinline__ void mma_f16(
    float& c0, float& c1, float& c2, float& c3,
    uint32_t a0, uint32_t a1, uint32_t a2, uint32_t a3,
    uint32_t b0, uint32_t b1)
{
    asm volatile(
        "mma.sync.aligned.m16n8k16.row.col.f32.f16.f16.f32 "
        "{%0,%1,%2,%3}, {%4,%5,%6,%7}, {%8,%9}, {%0,%1,%2,%3};"
        : "+f"(c0), "+f"(c1), "+f"(c2), "+f"(c3)
        : "r"(a0), "r"(a1), "r"(a2), "r"(a3), "r"(b0), "r"(b1));
}

// ---- pre-pass 1: x[b, off + k*D + i] -> x2[region + b*D + i][k] (fp16 RN) ----
__global__ void convert_x_kernel(const float* __restrict__ x)
{
    __shared__ float row[DIM];
    const int b = blockIdx.x;
    const float* src = x + (size_t)b * DIM;
    for (int v = threadIdx.x; v < DIM / 4; v += 256)
        *reinterpret_cast<float4*>(&row[v * 4]) =
            reinterpret_cast<const float4*>(src)[v];
    __syncthreads();
    // 9 output rows per batch: j=0 -> (m0,i0); j=1..3 -> (m1,i); j=4..8 -> (m2,i)
    for (int idx = threadIdx.x; idx < 9 * 256; idx += 256) {
        const int j  = idx >> 8;          // 0..8
        const int c2 = idx & 255;         // half2 index: k = 2*c2
        int off, D, i, grow;
        if (j == 0)      { off = 0;    D = 1; i = 0;     grow = X2_R1 + b; }
        else if (j < 4)  { off = 512;  D = 3; i = j - 1; grow = X2_R3 + b * 3 + i; }
        else             { off = 2048; D = 5; i = j - 4; grow = X2_R5 + b * 5 + i; }
        const float lo = row[off + (2 * c2    ) * D + i];
        const float hi = row[off + (2 * c2 + 1) * D + i];
        reinterpret_cast<__half2*>(x2_buf + (size_t)grow * MUL)[c2] =
            __floats2half2_rn(lo, hi);
    }
}

// ---- pre-pass 2: wT2[m][n][k] = fp16_rn(w_m[k][n]) ----
__global__ void transpose_w_kernel(const float* __restrict__ w0,
                                   const float* __restrict__ w1,
                                   const float* __restrict__ w2)
{
    __shared__ float tile[32][33];
    const int m = blockIdx.z;
    const float* src = (m == 0) ? w0 : (m == 1) ? w1 : w2;
    __half* dst = wT2_buf + m * MUL * MUL;
    const int kb = blockIdx.x * 32, nb = blockIdx.y * 32;
    #pragma unroll
    for (int i = threadIdx.y; i < 32; i += 8)
        tile[i][threadIdx.x] = src[(size_t)(kb + i) * MUL + nb + threadIdx.x];
    __syncthreads();
    #pragma unroll
    for (int i = threadIdx.y; i < 32; i += 8)
        dst[(size_t)(nb + i) * MUL + kb + threadIdx.x] =
            __float2half_rn(tile[threadIdx.x][i]);
}

template<int D, int R, int NWM, int NWN>
__device__ __forceinline__ void run_tile(
    const __half* __restrict__ x2, const __half* __restrict__ wT,
    const float* __restrict__ bias, float* __restrict__ out,
    int mt, int nt, int off, uint32_t smb)
{
    constexpr int WM    = R / NWM;
    constexpr int WN    = BN / NWN;
    constexpr int MFRAG = WM / 16;
    constexpr int NFRAG = WN / 8;
    constexpr int ACH   = R * 4;                 // 16B chunks per A stage
    constexpr int NAE   = (ACH + 255) / 256;
    static_assert(NWM * NWN == 8 && WM % 16 == 0 && NFRAG % 2 == 0, "layout");

    const int tid  = threadIdx.x;
    const int wid  = tid >> 5;
    const int lane = tid & 31;
    const int g    = lane >> 2;
    const int tig  = lane & 3;
    const int wm   = wid % NWM;
    const int wn   = wid / NWM;
    const int rt0  = mt * R;
    const int w0   = nt * BN;

    // ---- tile-invariant fill assignments (x2 rows are k-contiguous for ALL D) ----
    const __half* const xb = x2 + (size_t)rt0 * MUL;
    const __half* aptrg[NAE];
    uint32_t      aoffs[NAE];
    bool          aval [NAE];
    #pragma unroll
    for (int e = 0; e < NAE; e++) {
        const int v = tid + e * 256;
        const int r = v >> 2, kq = v & 3;
        aval[e]  = (v < ACH);
        aptrg[e] = xb + (size_t)r * MUL + kq * 8;
        aoffs[e] = (uint32_t)(r * LDA + kq * 16);
    }
    const __half* const wb = wT + (size_t)w0 * MUL;
    const __half* bptrg[2];
    uint32_t      boffs[2];
    #pragma unroll
    for (int e = 0; e < 2; e++) {
        const int v = tid + e * 256;
        const int n = v >> 2, kq = v & 3;
        bptrg[e] = wb + (size_t)n * MUL + kq * 8;
        boffs[e] = (uint32_t)(A_REG + n * LDB + kq * 16);
    }
    // ldmatrix lane-invariant offsets (80B strides: conflict-free bijections)
    const int a_row = (lane & 7) + ((lane >> 3) & 1) * 8;
    const int a_kh  = (lane >> 4) * 16;
    const uint32_t a_lm = (uint32_t)((wm * WM + a_row) * LDA + a_kh);
    const int b_row = (lane & 7) + (lane >> 4) * 8;
    const int b_kh  = ((lane >> 3) & 1) * 16;
    const uint32_t b_lm = (uint32_t)(A_REG + (wn * WN + b_row) * LDB + b_kh);

    float acc[MFRAG][NFRAG][4] = {};

    uint32_t stg[NSTG];
    #pragma unroll
    for (int s = 0; s < NSTG; s++) stg[s] = smb + s * STAGE;

    auto load_tile = [&](int t, uint32_t base) {
        const int tk = t * BK;               // halves offset along k
        #pragma unroll
        for (int e = 0; e < NAE; e++)
            if (aval[e]) cp16(base + aoffs[e], aptrg[e] + tk);
        #pragma unroll
        for (int e = 0; e < 2; e++)
            cp16(base + boffs[e], bptrg[e] + tk);
    };

    load_tile(0, stg[0]); cp_commit();
    load_tile(1, stg[1]); cp_commit();

    int cur = 0, nxt = 2;
    for (int t = 0; t < NKT; t++) {
        cp_wait1();
        __syncthreads();                     // stage t ready; stage nxt vacated
        if (t + 2 < NKT) load_tile(t + 2, stg[nxt]);
        cp_commit();

        const uint32_t Ac = stg[cur];
        #pragma unroll
        for (int s = 0; s < 2; s++) {        // two k16 steps in BK=32
            uint32_t afr[MFRAG][4];
            #pragma unroll
            for (int m = 0; m < MFRAG; m++)
                ldmx4(afr[m][0], afr[m][1], afr[m][2], afr[m][3],
                      Ac + a_lm + (uint32_t)(m * 16 * LDA + s * 32));
            uint32_t bfr[NFRAG][2];
            #pragma unroll
            for (int j = 0; j < NFRAG; j += 2)
                ldmx4(bfr[j][0], bfr[j][1], bfr[j + 1][0], bfr[j + 1][1],
                      Ac + b_lm + (uint32_t)(j * 8 * LDB + s * 32));
            #pragma unroll
            for (int m = 0; m < MFRAG; m++)
                #pragma unroll
                for (int n = 0; n < NFRAG; n++)
                    mma_f16(acc[m][n][0], acc[m][n][1], acc[m][n][2], acc[m][n][3],
                            afr[m][0], afr[m][1], afr[m][2], afr[m][3],
                            bfr[n][0], bfr[n][1]);
        }
        cur = (cur + 1 == NSTG) ? 0 : cur + 1;
        nxt = (nxt + 1 == NSTG) ? 0 : nxt + 1;
    }

    // ---- epilogue ----
    #pragma unroll
    for (int m = 0; m < MFRAG; m++) {
        #pragma unroll
        for (int half = 0; half < 2; half++) {
            const int row = wm * WM + m * 16 + g + half * 8;
            const int rg  = rt0 + row;
            const int b   = rg / D;
            const int i   = rg % D;
            float* orow = out + (size_t)b * DIM + off + i;
            #pragma unroll
            for (int n = 0; n < NFRAG; n++) {
                const int col = wn * WN + n * 8 + 2 * tig;
                #pragma unroll
                for (int e = 0; e < 2; e++) {
                    const int wc = w0 + col + e;
                    float v = acc[m][n][half * 2 + e] * PW;
                    if (D == 1) v += bias[wc];
                    orow[(size_t)wc * D] = v;
                }
            }
        }
    }
}

// D=1: R=128 -> 32 mtiles; D=3: R=96 -> 128; D=5: R=160 -> 128. x4 ntiles.
static constexpr int NB0 = 32 * 4;
static constexpr int NB1 = 128 * 4;
static constexpr int NB2 = 128 * 4;

__global__ __launch_bounds__(256, 2) void fused_irrep_kernel(
    const float* __restrict__ b0, float* __restrict__ out)
{
    extern __shared__ __align__(16) char sm[];
    const uint32_t smb = (uint32_t)__cvta_generic_to_shared(sm);
    const int bx = blockIdx.x;
    if (bx < NB0) {
        run_tile<1, 128, 2, 4>(x2_buf + (size_t)X2_R1 * MUL, wT2_buf,
                               b0, out, bx >> 2, bx & 3, 0, smb);
    } else if (bx < NB0 + NB1) {
        const int i = bx - NB0;
        run_tile<3,  96, 2, 4>(x2_buf + (size_t)X2_R3 * MUL, wT2_buf + MUL * MUL,
                               b0, out, i >> 2, i & 3, 512, smb);
    } else {
        const int i = bx - NB0 - NB1;
        run_tile<5, 160, 2, 4>(x2_buf + (size_t)X2_R5 * MUL, wT2_buf + 2 * MUL * MUL,
                               b0, out, i >> 2, i & 3, 2048, smb);
    }
}

extern "C" void kernel_launch(void* const* d_in, const int* in_sizes, int n_in,
                              void* d_out, int out_size)
{
    const float* x  = (const float*)d_in[0];
    const float* w0 = (const float*)d_in[1];
    const float* w1 = (const float*)d_in[2];
    const float* w2 = (const float*)d_in[3];
    const float* b0 = (const float*)d_in[4];
    float* out = (float*)d_out;

    convert_x_kernel<<<BATCH, 256>>>(x);
    transpose_w_kernel<<<dim3(MUL / 32, MUL / 32, 3), dim3(32, 8)>>>(w0, w1, w2);
    cudaFuncSetAttribute(fused_irrep_kernel,
                         cudaFuncAttributeMaxDynamicSharedMemorySize, SM_TOTAL);
    fused_irrep_kernel<<<NB0 + NB1 + NB2, 256, SM_TOTAL>>>(b0, out);
}

// round 11
// speedup vs baseline: 1.7879x; 1.0220x over previous
#include <cuda_runtime.h>
#include <cuda_fp16.h>
#include <cstdint>
#include <cstddef>

// Fused e3nn per-irrep linear, fp16 mma.sync m16n8k16 + fp32 accum.
// R11 = R10 + NSTG=4 pipeline (3-deep prefetch) + SMEM-staged coalesced
// epilogue (per-CTA output block is a contiguous 128*D-float span per batch).
//   out[b, off + w*D + i] = PW * sum_u W[u,w] * x[b, off + u*D + i]  (+bias, D==1)

static constexpr int MUL   = 512;
static constexpr int DIM   = 4608;
static constexpr int BATCH = 4096;
static constexpr int BN  = 128;
static constexpr int BK  = 32;
static constexpr int NKT = MUL / BK;          // 16 k-tiles
static constexpr float PW = 0.04419417382415922f;  // 512^-0.5

static constexpr int LDA   = 80;              // bytes per A row (32 halves + pad)
static constexpr int LDB   = 80;
static constexpr int A_REG = 160 * LDA;       // max R = 160 -> 12800 B
static constexpr int B_REG = BN * LDB;        // 10240 B
static constexpr int STAGE = A_REG + B_REG;   // 23040
static constexpr int NSTG  = 4;
static constexpr int SM_TOTAL = NSTG * STAGE; // 92160 B (also >= C tile 81920)

static constexpr int X2_R1 = 0;
static constexpr int X2_R3 = 4096;
static constexpr int X2_R5 = 4096 + 12288;
__device__ __half x2_buf[36864 * MUL];        // per-irrep GEMM-layout fp16 x
__device__ __half wT2_buf[3 * MUL * MUL];     // n-major fp16 weights

__device__ __forceinline__ void cp16(uint32_t s, const void* g) {
    asm volatile("cp.async.cg.shared.global [%0], [%1], 16;" :: "r"(s), "l"(g));
}
__device__ __forceinline__ void cp_commit() {
    asm volatile("cp.async.commit_group;" ::: "memory");
}
__device__ __forceinline__ void cp_wait2() {
    asm volatile("cp.async.wait_group 2;" ::: "memory");
}
__device__ __forceinline__ void ldmx4(uint32_t& r0, uint32_t& r1, uint32_t& r2,
                                      uint32_t& r3, uint32_t addr) {
    asm volatile("ldmatrix.sync.aligned.m8n8.x4.shared.b16 {%0,%1,%2,%3}, [%4];"
                 : "=r"(r0), "=r"(r1), "=r"(r2), "=r"(r3) : "r"(addr));
}
__device__ __forceinline__ void mma_f16(
    float& c0, float& c1, float& c2, float& c3,
    uint32_t a0, uint32_t a1, uint32_t a2, uint32_t a3,
    uint32_t b0, uint32_t b1)
{
    asm volatile(
        "mma.sync.aligned.m16n8k16.row.col.f32.f16.f16.f32 "
        "{%0,%1,%2,%3}, {%4,%5,%6,%7}, {%8,%9}, {%0,%1,%2,%3};"
        : "+f"(c0), "+f"(c1), "+f"(c2), "+f"(c3)
        : "r"(a0), "r"(a1), "r"(a2), "r"(a3), "r"(b0), "r"(b1));
}

// ---- pre-pass 1: x[b, off + k*D + i] -> x2[region + b*D + i][k] (fp16 RN) ----
__global__ void convert_x_kernel(const float* __restrict__ x)
{
    __shared__ float row[DIM];
    const int b = blockIdx.x;
    const float* src = x + (size_t)b * DIM;
    for (int v = threadIdx.x; v < DIM / 4; v += 256)
        *reinterpret_cast<float4*>(&row[v * 4]) =
            reinterpret_cast<const float4*>(src)[v];
    __syncthreads();
    for (int idx = threadIdx.x; idx < 9 * 256; idx += 256) {
        const int j  = idx >> 8;
        const int c2 = idx & 255;
        int off, D, i, grow;
        if (j == 0)      { off = 0;    D = 1; i = 0;     grow = X2_R1 + b; }
        else if (j < 4)  { off = 512;  D = 3; i = j - 1; grow = X2_R3 + b * 3 + i; }
        else             { off = 2048; D = 5; i = j - 4; grow = X2_R5 + b * 5 + i; }
        const float lo = row[off + (2 * c2    ) * D + i];
        const float hi = row[off + (2 * c2 + 1) * D + i];
        reinterpret_cast<__half2*>(x2_buf + (size_t)grow * MUL)[c2] =
            __floats2half2_rn(lo, hi);
    }
}

// ---- pre-pass 2: wT2[m][n][k] = fp16_rn(w_m[k][n]) ----
__global__ void transpose_w_kernel(const float* __restrict__ w0,
                                   const float* __restrict__ w1,
                                   const float* __restrict__ w2)
{
    __shared__ float tile[32][33];
    const int m = blockIdx.z;
    const float* src = (m == 0) ? w0 : (m == 1) ? w1 : w2;
    __half* dst = wT2_buf + m * MUL * MUL;
    const int kb = blockIdx.x * 32, nb = blockIdx.y * 32;
    #pragma unroll
    for (int i = threadIdx.y; i < 32; i += 8)
        tile[i][threadIdx.x] = src[(size_t)(kb + i) * MUL + nb + threadIdx.x];
    __syncthreads();
    #pragma unroll
    for (int i = threadIdx.y; i < 32; i += 8)
        dst[(size_t)(nb + i) * MUL + kb + threadIdx.x] =
            __float2half_rn(tile[threadIdx.x][i]);
}

template<int D, int R, int NWM, int NWN>
__device__ __forceinline__ void run_tile(
    const __half* __restrict__ x2, const __half* __restrict__ wT,
    const float* __restrict__ bias, float* __restrict__ out,
    int mt, int nt, int off, uint32_t smb, float* smf)
{
    constexpr int WM    = R / NWM;
    constexpr int WN    = BN / NWN;
    constexpr int MFRAG = WM / 16;
    constexpr int NFRAG = WN / 8;
    constexpr int ACH   = R * 4;
    constexpr int NAE   = (ACH + 255) / 256;
    static_assert(NWM * NWN == 8 && WM % 16 == 0 && NFRAG % 2 == 0, "layout");

    const int tid  = threadIdx.x;
    const int wid  = tid >> 5;
    const int lane = tid & 31;
    const int g    = lane >> 2;
    const int tig  = lane & 3;
    const int wm   = wid % NWM;
    const int wn   = wid / NWM;
    const int rt0  = mt * R;
    const int w0   = nt * BN;

    // ---- tile-invariant fill assignments ----
    const __half* const xb = x2 + (size_t)rt0 * MUL;
    const __half* aptrg[NAE];
    uint32_t      aoffs[NAE];
    bool          aval [NAE];
    #pragma unroll
    for (int e = 0; e < NAE; e++) {
        const int v = tid + e * 256;
        const int r = v >> 2, kq = v & 3;
        aval[e]  = (v < ACH);
        aptrg[e] = xb + (size_t)r * MUL + kq * 8;
        aoffs[e] = (uint32_t)(r * LDA + kq * 16);
    }
    const __half* const wb = wT + (size_t)w0 * MUL;
    const __half* bptrg[2];
    uint32_t      boffs[2];
    #pragma unroll
    for (int e = 0; e < 2; e++) {
        const int v = tid + e * 256;
        const int n = v >> 2, kq = v & 3;
        bptrg[e] = wb + (size_t)n * MUL + kq * 8;
        boffs[e] = (uint32_t)(A_REG + n * LDB + kq * 16);
    }
    const int a_row = (lane & 7) + ((lane >> 3) & 1) * 8;
    const int a_kh  = (lane >> 4) * 16;
    const uint32_t a_lm = (uint32_t)((wm * WM + a_row) * LDA + a_kh);
    const int b_row = (lane & 7) + (lane >> 4) * 8;
    const int b_kh  = ((lane >> 3) & 1) * 16;
    const uint32_t b_lm = (uint32_t)(A_REG + (wn * WN + b_row) * LDB + b_kh);

    float acc[MFRAG][NFRAG][4] = {};

    uint32_t stg[NSTG];
    #pragma unroll
    for (int s = 0; s < NSTG; s++) stg[s] = smb + s * STAGE;

    auto load_tile = [&](int t, uint32_t base) {
        const int tk = t * BK;
        #pragma unroll
        for (int e = 0; e < NAE; e++)
            if (aval[e]) cp16(base + aoffs[e], aptrg[e] + tk);
        #pragma unroll
        for (int e = 0; e < 2; e++)
            cp16(base + boffs[e], bptrg[e] + tk);
    };

    load_tile(0, stg[0]); cp_commit();
    load_tile(1, stg[1]); cp_commit();
    load_tile(2, stg[2]); cp_commit();

    for (int t = 0; t < NKT; t++) {
        cp_wait2();                      // load(t) complete; t+1,t+2 in flight
        __syncthreads();                 // all warps done with compute(t-1)
        if (t + 3 < NKT) load_tile(t + 3, stg[(t + 3) & 3]);
        cp_commit();

        const uint32_t Ac = stg[t & 3];
        #pragma unroll
        for (int s = 0; s < 2; s++) {
            uint32_t afr[MFRAG][4];
            #pragma unroll
            for (int m = 0; m < MFRAG; m++)
                ldmx4(afr[m][0], afr[m][1], afr[m][2], afr[m][3],
                      Ac + a_lm + (uint32_t)(m * 16 * LDA + s * 32));
            uint32_t bfr[NFRAG][2];
            #pragma unroll
            for (int j = 0; j < NFRAG; j += 2)
                ldmx4(bfr[j][0], bfr[j][1], bfr[j + 1][0], bfr[j + 1][1],
                      Ac + b_lm + (uint32_t)(j * 8 * LDB + s * 32));
            #pragma unroll
            for (int m = 0; m < MFRAG; m++)
                #pragma unroll
                for (int n = 0; n < NFRAG; n++)
                    mma_f16(acc[m][n][0], acc[m][n][1], acc[m][n][2], acc[m][n][3],
                            afr[m][0], afr[m][1], afr[m][2], afr[m][3],
                            bfr[n][0], bfr[n][1]);
        }
    }

    // ---- epilogue: stage C in SMEM (reuses pipeline buffers), write STG.128 ----
    __syncthreads();                     // mainloop fully done before overwriting
    #pragma unroll
    for (int m = 0; m < MFRAG; m++) {
        #pragma unroll
        for (int half = 0; half < 2; half++) {
            const int r = wm * WM + m * 16 + g + half * 8;
            #pragma unroll
            for (int n = 0; n < NFRAG; n++) {
                const int c = wn * WN + n * 8 + 2 * tig;
                smf[r * 128 + c    ] = acc[m][n][half * 2    ] * PW;
                smf[r * 128 + c + 1] = acc[m][n][half * 2 + 1] * PW;
            }
        }
    }
    __syncthreads();

    // per-batch contiguous span: out[b][off + w0*D + rem], rem in [0,128*D)
    constexpr int TOT4 = R * 128 / 4;
    const int bgl = rt0 / D;             // R is a multiple of D
    for (int p4 = tid; p4 < TOT4; p4 += 256) {
        const int p   = p4 * 4;
        const int bl  = p / (128 * D);
        const int rem = p - bl * (128 * D);
        float4 v;
        if constexpr (D == 1) {
            v = reinterpret_cast<const float4*>(smf)[p4];
            const float4 bb = *reinterpret_cast<const float4*>(bias + w0 + rem);
            v.x += bb.x; v.y += bb.y; v.z += bb.z; v.w += bb.w;
        } else {
            float tmp[4];
            #pragma unroll
            for (int j = 0; j < 4; j++) {
                const int rj = rem + j;
                tmp[j] = smf[(bl * D + rj % D) * 128 + rj / D];
            }
            v = make_float4(tmp[0], tmp[1], tmp[2], tmp[3]);
        }
        float* dst = out + (size_t)(bgl + bl) * DIM + off + w0 * D + rem;
        *reinterpret_cast<float4*>(dst) = v;
    }
}

// D=1: R=128 -> 32 mtiles; D=3: R=96 -> 128; D=5: R=160 -> 128. x4 ntiles.
static constexpr int NB0 = 32 * 4;
static constexpr int NB1 = 128 * 4;
static constexpr int NB2 = 128 * 4;

__global__ __launch_bounds__(256, 2) void fused_irrep_kernel(
    const float* __restrict__ b0, float* __restrict__ out)
{
    extern __shared__ __align__(16) char sm[];
    const uint32_t smb = (uint32_t)__cvta_generic_to_shared(sm);
    float* smf = reinterpret_cast<float*>(sm);
    const int bx = blockIdx.x;
    if (bx < NB0) {
        run_tile<1, 128, 2, 4>(x2_buf + (size_t)X2_R1 * MUL, wT2_buf,
                               b0, out, bx >> 2, bx & 3, 0, smb, smf);
    } else if (bx < NB0 + NB1) {
        const int i = bx - NB0;
        run_tile<3,  96, 2, 4>(x2_buf + (size_t)X2_R3 * MUL, wT2_buf + MUL * MUL,
                               b0, out, i >> 2, i & 3, 512, smb, smf);
    } else {
        const int i = bx - NB0 - NB1;
        run_tile<5, 160, 2, 4>(x2_buf + (size_t)X2_R5 * MUL, wT2_buf + 2 * MUL * MUL,
                               b0, out, i >> 2, i & 3, 2048, smb, smf);
    }
}

extern "C" void kernel_launch(void* const* d_in, const int* in_sizes, int n_in,
                              void* d_out, int out_size)
{
    const float* x  = (const float*)d_in[0];
    const float* w0 = (const float*)d_in[1];
    const float* w1 = (const float*)d_in[2];
    const float* w2 = (const float*)d_in[3];
    const float* b0 = (const float*)d_in[4];
    float* out = (float*)d_out;

    convert_x_kernel<<<BATCH, 256>>>(x);
    transpose_w_kernel<<<dim3(MUL / 32, MUL / 32, 3), dim3(32, 8)>>>(w0, w1, w2);
    cudaFuncSetAttribute(fused_irrep_kernel,
                         cudaFuncAttributeMaxDynamicSharedMemorySize, SM_TOTAL);
    fused_irrep_kernel<<<NB0 + NB1 + NB2, 256, SM_TOTAL>>>(b0, out);
}

// round 12
// speedup vs baseline: 1.8325x; 1.0249x over previous
#include <cuda_runtime.h>
#include <cuda_fp16.h>
#include <cstdint>
#include <cstddef>

// Fused e3nn per-irrep linear, fp16 mma.sync m16n8k16 + fp32 accum.
// R12 = R11 + warp-parity substep staggering (desync SMEM vs tensor phases)
//     + single merged pre-pass kernel (convert x + transpose W, PW folded into W).
//   out[b, off + w*D + i] = PW * sum_u W[u,w] * x[b, off + u*D + i]  (+bias, D==1)

static constexpr int MUL   = 512;
static constexpr int DIM   = 4608;
static constexpr int BATCH = 4096;
static constexpr int BN  = 128;
static constexpr int BK  = 32;
static constexpr int NKT = MUL / BK;          // 16 k-tiles
static constexpr float PW = 0.04419417382415922f;  // 512^-0.5 (folded into wT2)

static constexpr int LDA   = 80;
static constexpr int LDB   = 80;
static constexpr int A_REG = 160 * LDA;       // 12800 B (max R=160)
static constexpr int B_REG = BN * LDB;        // 10240 B
static constexpr int STAGE = A_REG + B_REG;   // 23040
static constexpr int NSTG  = 4;
static constexpr int SM_TOTAL = NSTG * STAGE; // 92160 B (>= C tile 81920)

static constexpr int X2_R1 = 0;
static constexpr int X2_R3 = 4096;
static constexpr int X2_R5 = 4096 + 12288;
__device__ __half x2_buf[36864 * MUL];
__device__ __half wT2_buf[3 * MUL * MUL];     // n-major, PW-prescaled fp16 weights

__device__ __forceinline__ void cp16(uint32_t s, const void* g) {
    asm volatile("cp.async.cg.shared.global [%0], [%1], 16;" :: "r"(s), "l"(g));
}
__device__ __forceinline__ void cp_commit() {
    asm volatile("cp.async.commit_group;" ::: "memory");
}
__device__ __forceinline__ void cp_wait2() {
    asm volatile("cp.async.wait_group 2;" ::: "memory");
}
__device__ __forceinline__ void ldmx4(uint32_t& r0, uint32_t& r1, uint32_t& r2,
                                      uint32_t& r3, uint32_t addr) {
    asm volatile("ldmatrix.sync.aligned.m8n8.x4.shared.b16 {%0,%1,%2,%3}, [%4];"
                 : "=r"(r0), "=r"(r1), "=r"(r2), "=r"(r3) : "r"(addr));
}
__device__ __forceinline__ void mma_f16(
    float& c0, float& c1, float& c2, float& c3,
    uint32_t a0, uint32_t a1, uint32_t a2, uint32_t a3,
    uint32_t b0, uint32_t b1)
{
    asm volatile(
        "mma.sync.aligned.m16n8k16.row.col.f32.f16.f16.f32 "
        "{%0,%1,%2,%3}, {%4,%5,%6,%7}, {%8,%9}, {%0,%1,%2,%3};"
        : "+f"(c0), "+f"(c1), "+f"(c2), "+f"(c3)
        : "r"(a0), "r"(a1), "r"(a2), "r"(a3), "r"(b0), "r"(b1));
}

// ---- merged pre-pass: blocks [0,BATCH) convert x; blocks [BATCH, BATCH+768) transpose W ----
__global__ void prep_kernel(const float* __restrict__ x,
                            const float* __restrict__ w0,
                            const float* __restrict__ w1,
                            const float* __restrict__ w2)
{
    __shared__ float buf[DIM];      // also used as 32x33 transpose tile (1056 floats)
    if (blockIdx.x < BATCH) {
        const int b = blockIdx.x;
        const float* src = x + (size_t)b * DIM;
        for (int v = threadIdx.x; v < DIM / 4; v += 256)
            *reinterpret_cast<float4*>(&buf[v * 4]) =
                reinterpret_cast<const float4*>(src)[v];
        __syncthreads();
        for (int idx = threadIdx.x; idx < 9 * 256; idx += 256) {
            const int j  = idx >> 8;
            const int c2 = idx & 255;
            int off, D, i, grow;
            if (j == 0)      { off = 0;    D = 1; i = 0;     grow = X2_R1 + b; }
            else if (j < 4)  { off = 512;  D = 3; i = j - 1; grow = X2_R3 + b * 3 + i; }
            else             { off = 2048; D = 5; i = j - 4; grow = X2_R5 + b * 5 + i; }
            const float lo = buf[off + (2 * c2    ) * D + i];
            const float hi = buf[off + (2 * c2 + 1) * D + i];
            reinterpret_cast<__half2*>(x2_buf + (size_t)grow * MUL)[c2] =
                __floats2half2_rn(lo, hi);
        }
    } else {
        // transpose: 768 blocks = 3 matrices x 16x16 tiles of 32x32
        const int tb = blockIdx.x - BATCH;
        const int m  = tb >> 8;
        const int r  = tb & 255;
        const int kb = (r >> 4) * 32, nb = (r & 15) * 32;
        const float* src = (m == 0) ? w0 : (m == 1) ? w1 : w2;
        __half* dst = wT2_buf + m * MUL * MUL;
        float (*tile)[33] = reinterpret_cast<float(*)[33]>(buf);
        const int tx = threadIdx.x & 31, ty = threadIdx.x >> 5;   // 32 x 8
        #pragma unroll
        for (int i = ty; i < 32; i += 8)
            tile[i][tx] = src[(size_t)(kb + i) * MUL + nb + tx];
        __syncthreads();
        #pragma unroll
        for (int i = ty; i < 32; i += 8)
            dst[(size_t)(nb + i) * MUL + kb + tx] =
                __float2half_rn(tile[tx][i] * PW);
    }
}

template<int D, int R, int NWM, int NWN>
__device__ __forceinline__ void run_tile(
    const __half* __restrict__ x2, const __half* __restrict__ wT,
    const float* __restrict__ bias, float* __restrict__ out,
    int mt, int nt, int off, uint32_t smb, float* smf)
{
    constexpr int WM    = R / NWM;
    constexpr int WN    = BN / NWN;
    constexpr int MFRAG = WM / 16;
    constexpr int NFRAG = WN / 8;
    constexpr int ACH   = R * 4;
    constexpr int NAE   = (ACH + 255) / 256;
    static_assert(NWM * NWN == 8 && WM % 16 == 0 && NFRAG % 2 == 0, "layout");

    const int tid  = threadIdx.x;
    const int wid  = tid >> 5;
    const int lane = tid & 31;
    const int g    = lane >> 2;
    const int tig  = lane & 3;
    const int wm   = wid % NWM;
    const int wn   = wid / NWM;
    const int rt0  = mt * R;
    const int w0   = nt * BN;

    const __half* const xb = x2 + (size_t)rt0 * MUL;
    const __half* aptrg[NAE];
    uint32_t      aoffs[NAE];
    bool          aval [NAE];
    #pragma unroll
    for (int e = 0; e < NAE; e++) {
        const int v = tid + e * 256;
        const int r = v >> 2, kq = v & 3;
        aval[e]  = (v < ACH);
        aptrg[e] = xb + (size_t)r * MUL + kq * 8;
        aoffs[e] = (uint32_t)(r * LDA + kq * 16);
    }
    const __half* const wb = wT + (size_t)w0 * MUL;
    const __half* bptrg[2];
    uint32_t      boffs[2];
    #pragma unroll
    for (int e = 0; e < 2; e++) {
        const int v = tid + e * 256;
        const int n = v >> 2, kq = v & 3;
        bptrg[e] = wb + (size_t)n * MUL + kq * 8;
        boffs[e] = (uint32_t)(A_REG + n * LDB + kq * 16);
    }
    const int a_row = (lane & 7) + ((lane >> 3) & 1) * 8;
    const int a_kh  = (lane >> 4) * 16;
    const uint32_t a_lm = (uint32_t)((wm * WM + a_row) * LDA + a_kh);
    const int b_row = (lane & 7) + (lane >> 4) * 8;
    const int b_kh  = ((lane >> 3) & 1) * 16;
    const uint32_t b_lm = (uint32_t)(A_REG + (wn * WN + b_row) * LDB + b_kh);

    float acc[MFRAG][NFRAG][4] = {};

    uint32_t stg[NSTG];
    #pragma unroll
    for (int s = 0; s < NSTG; s++) stg[s] = smb + s * STAGE;

    auto load_tile = [&](int t, uint32_t base) {
        const int tk = t * BK;
        #pragma unroll
        for (int e = 0; e < NAE; e++)
            if (aval[e]) cp16(base + aoffs[e], aptrg[e] + tk);
        #pragma unroll
        for (int e = 0; e < 2; e++)
            cp16(base + boffs[e], bptrg[e] + tk);
    };

    load_tile(0, stg[0]); cp_commit();
    load_tile(1, stg[1]); cp_commit();
    load_tile(2, stg[2]); cp_commit();

    const int s0 = wid & 1;              // stagger: odd warps reverse substep order
    for (int t = 0; t < NKT; t++) {
        cp_wait2();
        __syncthreads();
        if (t + 3 < NKT) load_tile(t + 3, stg[(t + 3) & 3]);
        cp_commit();

        const uint32_t Ac = stg[t & 3];
        #pragma unroll
        for (int si = 0; si < 2; si++) {
            const int s = si ^ s0;
            uint32_t afr[MFRAG][4];
            #pragma unroll
            for (int m = 0; m < MFRAG; m++)
                ldmx4(afr[m][0], afr[m][1], afr[m][2], afr[m][3],
                      Ac + a_lm + (uint32_t)(m * 16 * LDA + s * 32));
            uint32_t bfr[NFRAG][2];
            #pragma unroll
            for (int j = 0; j < NFRAG; j += 2)
                ldmx4(bfr[j][0], bfr[j][1], bfr[j + 1][0], bfr[j + 1][1],
                      Ac + b_lm + (uint32_t)(j * 8 * LDB + s * 32));
            #pragma unroll
            for (int m = 0; m < MFRAG; m++)
                #pragma unroll
                for (int n = 0; n < NFRAG; n++)
                    mma_f16(acc[m][n][0], acc[m][n][1], acc[m][n][2], acc[m][n][3],
                            afr[m][0], afr[m][1], afr[m][2], afr[m][3],
                            bfr[n][0], bfr[n][1]);
        }
    }

    // ---- epilogue: stage C in SMEM, coalesced STG.128 (PW already in wT2) ----
    __syncthreads();
    #pragma unroll
    for (int m = 0; m < MFRAG; m++) {
        #pragma unroll
        for (int half = 0; half < 2; half++) {
            const int r = wm * WM + m * 16 + g + half * 8;
            #pragma unroll
            for (int n = 0; n < NFRAG; n++) {
                const int c = wn * WN + n * 8 + 2 * tig;
                smf[r * 128 + c    ] = acc[m][n][half * 2    ];
                smf[r * 128 + c + 1] = acc[m][n][half * 2 + 1];
            }
        }
    }
    __syncthreads();

    constexpr int TOT4 = R * 128 / 4;
    const int bgl = rt0 / D;
    for (int p4 = tid; p4 < TOT4; p4 += 256) {
        const int p   = p4 * 4;
        const int bl  = p / (128 * D);
        const int rem = p - bl * (128 * D);
        float4 v;
        if constexpr (D == 1) {
            v = reinterpret_cast<const float4*>(smf)[p4];
            const float4 bb = *reinterpret_cast<const float4*>(bias + w0 + rem);
            v.x += bb.x; v.y += bb.y; v.z += bb.z; v.w += bb.w;
        } else {
            float tmp[4];
            #pragma unroll
            for (int j = 0; j < 4; j++) {
                const int rj = rem + j;
                tmp[j] = smf[(bl * D + rj % D) * 128 + rj / D];
            }
            v = make_float4(tmp[0], tmp[1], tmp[2], tmp[3]);
        }
        float* dst = out + (size_t)(bgl + bl) * DIM + off + w0 * D + rem;
        *reinterpret_cast<float4*>(dst) = v;
    }
}

static constexpr int NB0 = 32 * 4;
static constexpr int NB1 = 128 * 4;
static constexpr int NB2 = 128 * 4;

__global__ __launch_bounds__(256, 2) void fused_irrep_kernel(
    const float* __restrict__ b0, float* __restrict__ out)
{
    extern __shared__ __align__(16) char sm[];
    const uint32_t smb = (uint32_t)__cvta_generic_to_shared(sm);
    float* smf = reinterpret_cast<float*>(sm);
    const int bx = blockIdx.x;
    if (bx < NB0) {
        run_tile<1, 128, 2, 4>(x2_buf + (size_t)X2_R1 * MUL, wT2_buf,
                               b0, out, bx >> 2, bx & 3, 0, smb, smf);
    } else if (bx < NB0 + NB1) {
        const int i = bx - NB0;
        run_tile<3,  96, 2, 4>(x2_buf + (size_t)X2_R3 * MUL, wT2_buf + MUL * MUL,
                               b0, out, i >> 2, i & 3, 512, smb, smf);
    } else {
        const int i = bx - NB0 - NB1;
        run_tile<5, 160, 2, 4>(x2_buf + (size_t)X2_R5 * MUL, wT2_buf + 2 * MUL * MUL,
                               b0, out, i >> 2, i & 3, 2048, smb, smf);
    }
}

extern "C" void kernel_launch(void* const* d_in, const int* in_sizes, int n_in,
                              void* d_out, int out_size)
{
    const float* x  = (const float*)d_in[0];
    const float* w0 = (const float*)d_in[1];
    const float* w1 = (const float*)d_in[2];
    const float* w2 = (const float*)d_in[3];
    const float* b0 = (const float*)d_in[4];
    float* out = (float*)d_out;

    prep_kernel<<<BATCH + 768, 256>>>(x, w0, w1, w2);
    cudaFuncSetAttribute(fused_irrep_kernel,
                         cudaFuncAttributeMaxDynamicSharedMemorySize, SM_TOTAL);
    fused_irrep_kernel<<<NB0 + NB1 + NB2, 256, SM_TOTAL>>>(b0, out);
}